// round 1
// baseline (speedup 1.0000x reference)
#include <cuda_runtime.h>
#include <math.h>

#define BATCH   1024
#define NKPS    24
#define NEDGE   552           // 24*23
#define NHID    128
#define M_NODE  (BATCH*NKPS)  // 24576
#define M_EDGE  (BATCH*NEDGE) // 565248
#define BN_EPS  1e-5f

// ---------------- scratch (device globals; no allocation allowed) ----------
__device__ float g_bufA[(size_t)M_EDGE*NHID];   // m2 tmp -> h2 raw (x_skip)
__device__ float g_bufB[(size_t)M_EDGE*NHID];   // m4 tmp -> h4 raw
__device__ float g_n1[(size_t)M_NODE*NHID];     // m1 tmp -> x1 raw
__device__ float g_n2[(size_t)M_NODE*NHID];     // node2 input to m3; reused as node4
__device__ float g_n3[(size_t)M_NODE*NHID];     // m3 tmp -> h3 raw
__device__ float g_Wt[384*128];                 // transposed weight scratch [K,128]
__device__ float g_psum[(M_EDGE/128)*128];      // per-block partial sums
__device__ float g_psq [(M_EDGE/128)*128];
__device__ float g_s[4*128];                    // folded BN scale per stage
__device__ float g_t[4*128];                    // folded BN shift per stage

// ---------------- weight transpose: Wt[k*128+n] = W[n*K+k] ----------------
__global__ void transpose_w(const float* __restrict__ W, float* __restrict__ Wt, int K) {
    int idx = blockIdx.x * 256 + threadIdx.x;
    if (idx < K * 128) {
        int k = idx >> 7;
        int n = idx & 127;
        Wt[idx] = W[n * K + k];
    }
}

// ---------------- fused GEMM ------------------------------------------------
// out[M,128] = ELU( loader(A)[M,K] @ Wt[K,128] + bias ), optional per-block
// channel stats (sum, sumsq) written deterministically to psum/psq[block].
//
// MODE 0: plain A[M,K]
// MODE 2: edge gather, K=256: k<128 recv row of A (node feats), k<256 send row;
//         affine (sA1,tA1) applied to all 256 channels (s indexed k&127).
// MODE 3: edge gather, K=384: k<256 like MODE 2 on A (m3 nodes, sA1/tA1);
//         k>=256 skip connection A2[row,128] with affine (sA2,tA2).
template<int MODE>
__global__ __launch_bounds__(256)
void gemm_fused(const float* A, const float* A2,
                const float* __restrict__ W,      // pre-transposed [K,128]
                const float* __restrict__ bias,
                const float* __restrict__ sA1, const float* __restrict__ tA1,
                const float* __restrict__ sA2, const float* __restrict__ tA2,
                float* out, int K, int doStats,
                float* __restrict__ psum, float* __restrict__ psq)
{
    constexpr int BM = 128, BKT = 16, TM = 8, TN = 8;
    __shared__ float sh[4352];        // As: [128][17]=2176 floats, Bs: [16][128]=2048
    float* As = sh;                   // row-major [m][k], pad 17 (conflict-free)
    float* Bs = sh + 2176;            // [k][n]
    __shared__ int rowRecv[BM], rowSend[BM];
    __shared__ float sAf[384], tAf[384];

    const int tid  = threadIdx.x;
    const int bx   = blockIdx.x;
    const int row0 = bx * BM;
    const int tx   = tid & 15;        // n-group
    const int ty   = tid >> 4;        // m-group

    if (MODE != 0) {
        for (int m = tid; m < BM; m += 256) {
            int row = row0 + m;
            int b = row / NEDGE;
            int e = row - b * NEDGE;
            int r = e / 23;
            int j = e - r * 23;
            int s = j + (j >= r);
            rowRecv[m] = b * NKPS + r;
            rowSend[m] = b * NKPS + s;
        }
        for (int k = tid; k < K; k += 256) {
            if (k < 256) { sAf[k] = sA1[k & 127]; tAf[k] = tA1[k & 127]; }
            else         { sAf[k] = sA2[k - 256]; tAf[k] = tA2[k - 256]; }
        }
    }
    __syncthreads();

    float acc[TM][TN];
#pragma unroll
    for (int i = 0; i < TM; i++)
#pragma unroll
        for (int j = 0; j < TN; j++) acc[i][j] = 0.f;

    for (int k0 = 0; k0 < K; k0 += BKT) {
        // ---- load A tile: 128x16 floats, 2 float4 per thread ----
#pragma unroll
        for (int i = 0; i < 2; i++) {
            int idx4 = tid + i * 256;
            int m  = idx4 >> 2;
            int ks = (idx4 & 3) * 4;
            int kk = k0 + ks;
            float4 v;
            if (MODE == 0) {
                const float* p = A + (size_t)(row0 + m) * K + kk;
                if (((K & 3) == 0) && (kk + 3 < K)) {
                    v = *(const float4*)p;
                } else {
                    v.x = (kk     < K) ? p[0] : 0.f;
                    v.y = (kk + 1 < K) ? p[1] : 0.f;
                    v.z = (kk + 2 < K) ? p[2] : 0.f;
                    v.w = (kk + 3 < K) ? p[3] : 0.f;
                }
            } else {
                const float* src;
                if (kk < 128)        src = A  + (size_t)rowRecv[m] * 128 + kk;
                else if (kk < 256)   src = A  + (size_t)rowSend[m] * 128 + (kk - 128);
                else                 src = A2 + (size_t)(row0 + m) * 128 + (kk - 256);
                v = *(const float4*)src;
                v.x = fmaf(v.x, sAf[kk],     tAf[kk]);
                v.y = fmaf(v.y, sAf[kk + 1], tAf[kk + 1]);
                v.z = fmaf(v.z, sAf[kk + 2], tAf[kk + 2]);
                v.w = fmaf(v.w, sAf[kk + 3], tAf[kk + 3]);
            }
            float* a = As + m * 17 + ks;
            a[0] = v.x; a[1] = v.y; a[2] = v.z; a[3] = v.w;
        }
        // ---- load B tile: 16x128 floats, 2 float4 per thread ----
#pragma unroll
        for (int i = 0; i < 2; i++) {
            int idx4 = tid + i * 256;
            int k  = idx4 >> 5;
            int n4 = (idx4 & 31) * 4;
            float4 v = make_float4(0.f, 0.f, 0.f, 0.f);
            if (k0 + k < K) v = *(const float4*)(W + (size_t)(k0 + k) * 128 + n4);
            *(float4*)&Bs[k * 128 + n4] = v;
        }
        __syncthreads();

#pragma unroll
        for (int k = 0; k < BKT; k++) {
            float a[TM];
#pragma unroll
            for (int i = 0; i < TM; i++) a[i] = As[(ty * TM + i) * 17 + k];
            float4 b0 = *(const float4*)&Bs[k * 128 + tx * 8];
            float4 b1 = *(const float4*)&Bs[k * 128 + tx * 8 + 4];
            float b[TN] = {b0.x, b0.y, b0.z, b0.w, b1.x, b1.y, b1.z, b1.w};
#pragma unroll
            for (int i = 0; i < TM; i++)
#pragma unroll
                for (int j = 0; j < TN; j++) acc[i][j] = fmaf(a[i], b[j], acc[i][j]);
        }
        __syncthreads();
    }

    // ---- epilogue: bias + ELU, store, deterministic per-block stats ----
    float cs[TN], cq[TN];
#pragma unroll
    for (int j = 0; j < TN; j++) { cs[j] = 0.f; cq[j] = 0.f; }

    float bcol[TN];
#pragma unroll
    for (int j = 0; j < TN; j++) bcol[j] = bias[tx * 8 + j];

#pragma unroll
    for (int i = 0; i < TM; i++) {
        int gr = row0 + ty * TM + i;
        float v[TN];
#pragma unroll
        for (int j = 0; j < TN; j++) {
            float r = acc[i][j] + bcol[j];
            float e = (r > 0.f) ? r : expm1f(r);
            v[j] = e;
            cs[j] += e;
            cq[j] += e * e;
        }
        float4* o = (float4*)(out + (size_t)gr * 128 + tx * 8);
        o[0] = make_float4(v[0], v[1], v[2], v[3]);
        o[1] = make_float4(v[4], v[5], v[6], v[7]);
    }

    if (doStats) {
        float* sS = sh;          // 16*128 = 2048
        float* sQ = sh + 2048;   // 16*128 = 2048 (fits in 4352)
#pragma unroll
        for (int j = 0; j < TN; j++) {
            sS[ty * 128 + tx * 8 + j] = cs[j];
            sQ[ty * 128 + tx * 8 + j] = cq[j];
        }
        __syncthreads();
        if (tid < 128) {
            float s = 0.f, q = 0.f;
#pragma unroll
            for (int i = 0; i < 16; i++) { s += sS[i * 128 + tid]; q += sQ[i * 128 + tid]; }
            psum[(size_t)bx * 128 + tid] = s;
            psq [(size_t)bx * 128 + tid] = q;
        }
    }
}

// ---------------- BN finalize: fold stats into (s,t) -----------------------
__global__ void bn_finalize(const float* __restrict__ psum, const float* __restrict__ psq,
                            int nblocks, float Minv,
                            const float* __restrict__ g, const float* __restrict__ be,
                            float* __restrict__ s, float* __restrict__ t)
{
    int c = threadIdx.x;   // 128 threads
    float S = 0.f, Q = 0.f;
    for (int i = 0; i < nblocks; i++) {
        S += psum[(size_t)i * 128 + c];
        Q += psq [(size_t)i * 128 + c];
    }
    float mean = S * Minv;
    float var  = Q * Minv - mean * mean;
    float inv  = rsqrtf(var + BN_EPS);
    float sv   = g[c] * inv;
    s[c] = sv;
    t[c] = be[c] - mean * sv;
}

// ---------------- edge2node: node[bn,c] = (s*sum_{23 edges} h + 23*t)/24 ----
__global__ void edge2node(const float* __restrict__ h,
                          const float* __restrict__ s, const float* __restrict__ t,
                          float* __restrict__ outn)
{
    int c  = threadIdx.x;           // 128
    int bn = blockIdx.x;            // b*24+n ; edges start at bn*23 (552 = 24*23)
    const float* p = h + (size_t)bn * 23 * 128 + c;
    float acc = 0.f;
#pragma unroll
    for (int j = 0; j < 23; j++) acc += p[(size_t)j * 128];
    outn[(size_t)bn * 128 + c] = (s[c] * acc + 23.f * t[c]) * (1.f / 24.f);
}

// ---------------- final projection: out[b,o] = node4[b,:] . fo_w[o,:] + b ---
__global__ void final_proj(const float* __restrict__ node4,
                           const float* __restrict__ fo_w, const float* __restrict__ fo_b,
                           float* __restrict__ out)
{
    int b = blockIdx.x;
    int c = threadIdx.x;   // 128
    float a0 = 0.f, a1 = 0.f;
#pragma unroll
    for (int n = 0; n < NKPS; n++) {
        float v = node4[((size_t)b * NKPS + n) * 128 + c];
        a0 = fmaf(v, fo_w[n * 128 + c],        a0);
        a1 = fmaf(v, fo_w[3072 + n * 128 + c], a1);
    }
    __shared__ float r0[128], r1[128];
    r0[c] = a0; r1[c] = a1;
    __syncthreads();
    for (int off = 64; off; off >>= 1) {
        if (c < off) { r0[c] += r0[c + off]; r1[c] += r1[c + off]; }
        __syncthreads();
    }
    if (c == 0) {
        out[b * 2 + 0] = r0[0] + fo_b[0];
        out[b * 2 + 1] = r1[0] + fo_b[1];
    }
}

// ---------------- launch ----------------------------------------------------
extern "C" void kernel_launch(void* const* d_in, const int* in_sizes, int n_in,
                              void* d_out, int out_size)
{
    const float* inputs = (const float*)d_in[0];
    // d_in[1]=rel_rec, d_in[2]=rel_send: structure is fixed, derived analytically
    const float* fo_w = (const float*)d_in[3];
    const float* fo_b = (const float*)d_in[4];
    const float* m1w1 = (const float*)d_in[5];
    const float* m1b1 = (const float*)d_in[6];
    const float* m1w2 = (const float*)d_in[7];
    const float* m1b2 = (const float*)d_in[8];
    const float* m1g  = (const float*)d_in[9];
    const float* m1be = (const float*)d_in[10];
    const float* m2w1 = (const float*)d_in[11];
    const float* m2b1 = (const float*)d_in[12];
    const float* m2w2 = (const float*)d_in[13];
    const float* m2b2 = (const float*)d_in[14];
    const float* m2g  = (const float*)d_in[15];
    const float* m2be = (const float*)d_in[16];
    const float* m3w1 = (const float*)d_in[17];
    const float* m3b1 = (const float*)d_in[18];
    const float* m3w2 = (const float*)d_in[19];
    const float* m3b2 = (const float*)d_in[20];
    const float* m3g  = (const float*)d_in[21];
    const float* m3be = (const float*)d_in[22];
    const float* m4w1 = (const float*)d_in[23];
    const float* m4b1 = (const float*)d_in[24];
    const float* m4w2 = (const float*)d_in[25];
    const float* m4b2 = (const float*)d_in[26];
    const float* m4g  = (const float*)d_in[27];
    const float* m4be = (const float*)d_in[28];
    float* out = (float*)d_out;

    float *bufA, *bufB, *n1, *n2, *n3, *Wt, *psum, *psq, *sArr, *tArr;
    cudaGetSymbolAddress((void**)&bufA, g_bufA);
    cudaGetSymbolAddress((void**)&bufB, g_bufB);
    cudaGetSymbolAddress((void**)&n1,   g_n1);
    cudaGetSymbolAddress((void**)&n2,   g_n2);
    cudaGetSymbolAddress((void**)&n3,   g_n3);
    cudaGetSymbolAddress((void**)&Wt,   g_Wt);
    cudaGetSymbolAddress((void**)&psum, g_psum);
    cudaGetSymbolAddress((void**)&psq,  g_psq);
    cudaGetSymbolAddress((void**)&sArr, g_s);
    cudaGetSymbolAddress((void**)&tArr, g_t);

    const int GN = M_NODE / 128;   // 192
    const int GE = M_EDGE / 128;   // 4416
    const float MinvN = 1.0f / (float)M_NODE;
    const float MinvE = 1.0f / (float)M_EDGE;

    // ---- stage 1 (nodes): K=6 then K=128, stats -> s/t[0]
    transpose_w<<<(6 * 128 + 255) / 256, 256>>>(m1w1, Wt, 6);
    gemm_fused<0><<<GN, 256>>>(inputs, nullptr, Wt, m1b1,
                               nullptr, nullptr, nullptr, nullptr,
                               n1, 6, 0, psum, psq);
    transpose_w<<<(128 * 128 + 255) / 256, 256>>>(m1w2, Wt, 128);
    gemm_fused<0><<<GN, 256>>>(n1, nullptr, Wt, m1b2,
                               nullptr, nullptr, nullptr, nullptr,
                               n1, 128, 1, psum, psq);
    bn_finalize<<<1, 128>>>(psum, psq, GN, MinvN, m1g, m1be, sArr + 0, tArr + 0);

    // ---- stage 2 (edges): gather(K=256) then K=128, stats -> s/t[1]
    transpose_w<<<(256 * 128 + 255) / 256, 256>>>(m2w1, Wt, 256);
    gemm_fused<2><<<GE, 256>>>(n1, nullptr, Wt, m2b1,
                               sArr + 0, tArr + 0, nullptr, nullptr,
                               bufA, 256, 0, psum, psq);
    transpose_w<<<(128 * 128 + 255) / 256, 256>>>(m2w2, Wt, 128);
    gemm_fused<0><<<GE, 256>>>(bufA, nullptr, Wt, m2b2,
                               nullptr, nullptr, nullptr, nullptr,
                               bufA, 128, 1, psum, psq);
    bn_finalize<<<1, 128>>>(psum, psq, GE, MinvE, m2g, m2be, sArr + 128, tArr + 128);

    // ---- edge2node of normalized h2 -> node2
    edge2node<<<M_NODE, 128>>>(bufA, sArr + 128, tArr + 128, n2);

    // ---- stage 3 (nodes): K=128, K=128, stats -> s/t[2]
    transpose_w<<<(128 * 128 + 255) / 256, 256>>>(m3w1, Wt, 128);
    gemm_fused<0><<<GN, 256>>>(n2, nullptr, Wt, m3b1,
                               nullptr, nullptr, nullptr, nullptr,
                               n3, 128, 0, psum, psq);
    transpose_w<<<(128 * 128 + 255) / 256, 256>>>(m3w2, Wt, 128);
    gemm_fused<0><<<GN, 256>>>(n3, nullptr, Wt, m3b2,
                               nullptr, nullptr, nullptr, nullptr,
                               n3, 128, 1, psum, psq);
    bn_finalize<<<1, 128>>>(psum, psq, GN, MinvN, m3g, m3be, sArr + 256, tArr + 256);

    // ---- stage 4 (edges): gather(K=384: recv/send of h3 + skip h2), stats -> s/t[3]
    transpose_w<<<(384 * 128 + 255) / 256, 256>>>(m4w1, Wt, 384);
    gemm_fused<3><<<GE, 256>>>(n3, bufA, Wt, m4b1,
                               sArr + 256, tArr + 256, sArr + 128, tArr + 128,
                               bufB, 384, 0, psum, psq);
    transpose_w<<<(128 * 128 + 255) / 256, 256>>>(m4w2, Wt, 128);
    gemm_fused<0><<<GE, 256>>>(bufB, nullptr, Wt, m4b2,
                               nullptr, nullptr, nullptr, nullptr,
                               bufB, 128, 1, psum, psq);
    bn_finalize<<<1, 128>>>(psum, psq, GE, MinvE, m4g, m4be, sArr + 384, tArr + 384);

    // ---- edge2node of normalized h4 -> node4 (reuse n2), final projection
    edge2node<<<M_NODE, 128>>>(bufB, sArr + 384, tArr + 384, n2);
    final_proj<<<BATCH, 128>>>(n2, fo_w, fo_b, out);
}

// round 3
// speedup vs baseline: 1.6541x; 1.6541x over previous
#include <cuda_runtime.h>
#include <math.h>
#include <stdint.h>

#define BATCH   1024
#define NKPS    24
#define NEDGE   552
#define M_NODE  (BATCH*NKPS)    // 24576
#define M_EDGE  (BATCH*NEDGE)   // 565248
#define BN_EPS  1e-5f

// ---------------- scratch (device globals) ---------------------------------
__device__ float g_bufA[(size_t)M_EDGE*128];   // raw h2 (x_skip)
__device__ float g_bufB[(size_t)M_EDGE*128];   // raw h4
__device__ float g_n1 [(size_t)M_NODE*128];    // raw x1
__device__ float g_n2 [(size_t)M_NODE*128];    // node2 / node4
__device__ float g_n3 [(size_t)M_NODE*128];    // raw h3
__device__ float g_xpad[(size_t)M_NODE*32];    // inputs padded 6 -> 32
__device__ float g_w1e[384*128];               // folded layer-1 weights [n][K1PAD]
__device__ float g_beff[128];                  // folded layer-1 bias
__device__ float g_psum[(M_EDGE/128)*128];
__device__ float g_psq [(M_EDGE/128)*128];
__device__ float g_s[4*128];
__device__ float g_t[4*128];

// ---------------- small helpers ---------------------------------------------
__device__ __forceinline__ uint32_t smem_u32(const void* p) {
    uint32_t a;
    asm("{ .reg .u64 t; cvta.to.shared.u64 t, %1; cvt.u32.u64 %0, t; }" : "=r"(a) : "l"(p));
    return a;
}
__device__ __forceinline__ void cp16(uint32_t dst, const void* src) {
    asm volatile("cp.async.cg.shared.global [%0], [%1], 16;" :: "r"(dst), "l"(src));
}
__device__ __forceinline__ uint32_t f2tf(float x) {
    uint32_t u;
    asm("cvt.rna.tf32.f32 %0, %1;" : "=r"(u) : "f"(x));
    return u;
}
__device__ __forceinline__ void mma8(float d[4],
                                     uint32_t a0, uint32_t a1, uint32_t a2, uint32_t a3,
                                     uint32_t b0, uint32_t b1) {
    asm volatile("mma.sync.aligned.m16n8k8.row.col.f32.tf32.tf32.f32 "
        "{%0,%1,%2,%3}, {%4,%5,%6,%7}, {%8,%9}, {%0,%1,%2,%3};"
        : "+f"(d[0]), "+f"(d[1]), "+f"(d[2]), "+f"(d[3])
        : "r"(a0), "r"(a1), "r"(a2), "r"(a3), "r"(b0), "r"(b1));
}

// ---------------- SMEM layout (bytes) ----------------------------------------
// chunk tiles: [128 rows][32 cols] stride 36 floats (144B) -> 18432B each
// A2/W2 tiles: [128][128] stride 132 floats (528B) -> 67584B each
#define OFF_RECV   0
#define OFF_SEND   512
#define OFF_BE     1024
#define OFF_B2V    1536
#define OFF_CHA    2048                 /* 2 x 18432 */
#define OFF_CHW    38912                /* 2 x 18432 */
#define OFF_A2     75776                /* 67584 */
#define OFF_W2     143360               /* 67584 */
#define SMEM_TOTAL 210944

// ---------------- fused 2-layer MLP, mma.sync tf32 ---------------------------
// MODE 0: A plain [M][K1PAD] (rows padded, 16B aligned)
// MODE 2: edge gather K1=256 (recv|send rows of A[M_NODE][128])
// MODE 3: edge gather K1=384 (recv|send rows of A + contiguous skip rows of Askip)
template<int MODE, int K1PAD>
__global__ __launch_bounds__(256, 1)
void mlp2(const float* __restrict__ A, const float* __restrict__ Askip,
          const float* __restrict__ W1e,   // [128][K1PAD] folded (scaled) weights
          const float* __restrict__ beff,  // [128] folded bias
          const float* __restrict__ W2,    // [128][128] raw
          const float* __restrict__ b2,
          float* __restrict__ out,
          float* __restrict__ psum, float* __restrict__ psq)
{
    extern __shared__ char smem[];
    float* smf = (float*)smem;
    const uint32_t sb = smem_u32(smem);
    const int tid = threadIdx.x;
    const int wid = tid >> 5, lid = tid & 31;
    const int g = lid >> 2, tg = lid & 3;          // mma fragment coords
    const int wm = wid & 3, wn = wid >> 2;         // warp tile: rows wm*32, cols wn*64
    const int row0 = blockIdx.x * 128;
    int* rs = (int*)(smem + OFF_RECV);
    int* ss = (int*)(smem + OFF_SEND);

    // ---- setup ----
    if (MODE != 0 && tid < 128) {
        int row = row0 + tid;
        int b = row / NEDGE;
        int e = row - b * NEDGE;
        int r = e / 23;
        int j = e - r * 23;
        int s = j + (j >= r);
        rs[tid] = b * NKPS + r;
        ss[tid] = b * NKPS + s;
    }
    if (tid < 128) {
        smf[OFF_BE/4  + tid] = beff[tid];
        smf[OFF_B2V/4 + tid] = b2[tid];
    }
    __syncthreads();

    // ---- group 0: W2 prefetch (completes before first wait_group returns old groups) ----
#pragma unroll
    for (int i = 0; i < 16; i++) {
        int idx4 = i * 256 + tid;                   // 4096 float4
        int row = idx4 >> 5, c4 = idx4 & 31;
        cp16(sb + OFF_W2 + row * 528 + c4 * 16, W2 + (size_t)row * 128 + c4 * 4);
    }
    asm volatile("cp.async.commit_group;");

    constexpr int NCH = K1PAD / 32;

    auto issue_chunk = [&](int c, int buf) {
        const int kb = c * 32;
#pragma unroll
        for (int i = 0; i < 4; i++) {
            int idx4 = i * 256 + tid;               // 1024 float4
            int row = idx4 >> 3, c4 = idx4 & 7;
            int kk = kb + c4 * 4;
            const float* src;
            if (MODE == 0) {
                src = A + (size_t)(row0 + row) * K1PAD + kk;
            } else {
                if (kk < 128)      src = A + (size_t)rs[row] * 128 + kk;
                else if (kk < 256) src = A + (size_t)ss[row] * 128 + (kk - 128);
                else               src = Askip + (size_t)(row0 + row) * 128 + (kk - 256);
            }
            cp16(sb + OFF_CHA + buf * 18432 + row * 144 + c4 * 16, src);
            cp16(sb + OFF_CHW + buf * 18432 + row * 144 + c4 * 16,
                 W1e + (size_t)row * K1PAD + kk);
        }
        asm volatile("cp.async.commit_group;");
    };

    issue_chunk(0, 0);
    if (NCH > 1) issue_chunk(1, 1);

    float acc[2][8][4];
#pragma unroll
    for (int f = 0; f < 2; f++)
#pragma unroll
        for (int nt = 0; nt < 8; nt++)
#pragma unroll
            for (int q = 0; q < 4; q++) acc[f][nt][q] = 0.f;

    // ---- layer 1: K1PAD in chunks of 32 ----
    for (int c = 0; c < NCH; c++) {
        const int buf = c & 1;
        if (c + 1 < NCH) asm volatile("cp.async.wait_group 1;");
        else             asm volatile("cp.async.wait_group 0;");
        __syncthreads();

        const float* As = smf + (OFF_CHA + buf * 18432) / 4;
        const float* Ws = smf + (OFF_CHW + buf * 18432) / 4;
#pragma unroll
        for (int ks = 0; ks < 4; ks++) {
            uint32_t a[2][4];
#pragma unroll
            for (int f = 0; f < 2; f++) {
                const float* p = As + (wm * 32 + f * 16 + g) * 36 + ks * 8 + tg;
                a[f][0] = f2tf(p[0]);
                a[f][1] = f2tf(p[8 * 36]);
                a[f][2] = f2tf(p[4]);
                a[f][3] = f2tf(p[8 * 36 + 4]);
            }
#pragma unroll
            for (int nt = 0; nt < 8; nt++) {
                const float* q = Ws + (wn * 64 + nt * 8 + g) * 36 + ks * 8 + tg;
                uint32_t b0 = f2tf(q[0]);
                uint32_t b1 = f2tf(q[4]);
                mma8(acc[0][nt], a[0][0], a[0][1], a[0][2], a[0][3], b0, b1);
                mma8(acc[1][nt], a[1][0], a[1][1], a[1][2], a[1][3], b0, b1);
            }
        }
        __syncthreads();
        if (c + 2 < NCH) issue_chunk(c + 2, buf);
    }

    // ---- epilogue 1: bias + ELU -> A2 (SMEM), reset acc ----
    {
        float* A2 = smf + OFF_A2 / 4;
#pragma unroll
        for (int f = 0; f < 2; f++) {
            int r = wm * 32 + f * 16 + g;
#pragma unroll
            for (int nt = 0; nt < 8; nt++) {
                int n0 = wn * 64 + nt * 8 + tg * 2;
                float be0 = smf[OFF_BE/4 + n0], be1 = smf[OFF_BE/4 + n0 + 1];
                float v0 = acc[f][nt][0] + be0;
                float v1 = acc[f][nt][1] + be1;
                float v2 = acc[f][nt][2] + be0;
                float v3 = acc[f][nt][3] + be1;
                v0 = (v0 > 0.f) ? v0 : expm1f(v0);
                v1 = (v1 > 0.f) ? v1 : expm1f(v1);
                v2 = (v2 > 0.f) ? v2 : expm1f(v2);
                v3 = (v3 > 0.f) ? v3 : expm1f(v3);
                *(float2*)(A2 + r * 132 + n0)       = make_float2(v0, v1);
                *(float2*)(A2 + (r + 8) * 132 + n0) = make_float2(v2, v3);
#pragma unroll
                for (int q = 0; q < 4; q++) acc[f][nt][q] = 0.f;
            }
        }
    }
    __syncthreads();

    // ---- layer 2: D2 = A2 @ W2^T, K=128 from SMEM ----
    {
        const float* As = smf + OFF_A2 / 4;
        const float* Ws = smf + OFF_W2 / 4;
#pragma unroll 4
        for (int ks = 0; ks < 16; ks++) {
            uint32_t a[2][4];
#pragma unroll
            for (int f = 0; f < 2; f++) {
                const float* p = As + (wm * 32 + f * 16 + g) * 132 + ks * 8 + tg;
                a[f][0] = f2tf(p[0]);
                a[f][1] = f2tf(p[8 * 132]);
                a[f][2] = f2tf(p[4]);
                a[f][3] = f2tf(p[8 * 132 + 4]);
            }
#pragma unroll
            for (int nt = 0; nt < 8; nt++) {
                const float* q = Ws + (wn * 64 + nt * 8 + g) * 132 + ks * 8 + tg;
                uint32_t b0 = f2tf(q[0]);
                uint32_t b1 = f2tf(q[4]);
                mma8(acc[0][nt], a[0][0], a[0][1], a[0][2], a[0][3], b0, b1);
                mma8(acc[1][nt], a[1][0], a[1][1], a[1][2], a[1][3], b0, b1);
            }
        }
    }
    __syncthreads();   // all A2 reads done before overwrite

    // ---- epilogue 2: bias + ELU -> A2, then coalesced store + stats ----
    {
        float* A2 = smf + OFF_A2 / 4;
#pragma unroll
        for (int f = 0; f < 2; f++) {
            int r = wm * 32 + f * 16 + g;
#pragma unroll
            for (int nt = 0; nt < 8; nt++) {
                int n0 = wn * 64 + nt * 8 + tg * 2;
                float be0 = smf[OFF_B2V/4 + n0], be1 = smf[OFF_B2V/4 + n0 + 1];
                float v0 = acc[f][nt][0] + be0;
                float v1 = acc[f][nt][1] + be1;
                float v2 = acc[f][nt][2] + be0;
                float v3 = acc[f][nt][3] + be1;
                v0 = (v0 > 0.f) ? v0 : expm1f(v0);
                v1 = (v1 > 0.f) ? v1 : expm1f(v1);
                v2 = (v2 > 0.f) ? v2 : expm1f(v2);
                v3 = (v3 > 0.f) ? v3 : expm1f(v3);
                *(float2*)(A2 + r * 132 + n0)       = make_float2(v0, v1);
                *(float2*)(A2 + (r + 8) * 132 + n0) = make_float2(v2, v3);
            }
        }
    }
    __syncthreads();
    {
        const float* A2 = smf + OFF_A2 / 4;
#pragma unroll
        for (int i = 0; i < 16; i++) {
            int idx4 = i * 256 + tid;
            int row = idx4 >> 5, c4 = idx4 & 31;
            float4 v = *(const float4*)(A2 + row * 132 + c4 * 4);
            *(float4*)(out + (size_t)(row0 + row) * 128 + c4 * 4) = v;
        }
        if (tid < 128) {
            float S = 0.f, Q = 0.f;
#pragma unroll 8
            for (int r = 0; r < 128; r++) {
                float x = A2[r * 132 + tid];
                S += x;
                Q += x * x;
            }
            psum[(size_t)blockIdx.x * 128 + tid] = S;
            psq [(size_t)blockIdx.x * 128 + tid] = Q;
        }
    }
}

// ---------------- prep: fold BN affine into layer-1 weights ------------------
// W1e[n][k] = W1[n][k]*s(k);  beff[n] = b1[n] + sum_k W1[n][k]*t(k)
// k < 256 -> (sA,tA)[k&127]; k >= 256 -> (sB,tB)[k-256]; null sA -> identity
__global__ void prep_w(const float* __restrict__ W1, const float* __restrict__ b1,
                       int k1real, int K1PAD,
                       const float* __restrict__ sA, const float* __restrict__ tA,
                       const float* __restrict__ sB, const float* __restrict__ tB,
                       float* __restrict__ W1e, float* __restrict__ beff)
{
    const int n = blockIdx.x;
    const int tid = threadIdx.x;   // 256
    float partial = 0.f;
    for (int k = tid; k < K1PAD; k += 256) {
        float w = (k < k1real) ? W1[(size_t)n * k1real + k] : 0.f;
        float s = 1.f, t = 0.f;
        if (k < k1real) {
            if (k < 256) { if (sA) { s = sA[k & 127]; t = tA[k & 127]; } }
            else         { s = sB[k - 256]; t = tB[k - 256]; }
        }
        W1e[(size_t)n * K1PAD + k] = w * s;
        partial += w * t;
    }
    __shared__ float red[256];
    red[tid] = partial;
    __syncthreads();
    for (int off = 128; off; off >>= 1) {
        if (tid < off) red[tid] += red[tid + off];
        __syncthreads();
    }
    if (tid == 0) beff[n] = b1[n] + red[0];
}

// ---------------- pad inputs 6 -> 32 cols ------------------------------------
__global__ void pad_inputs(const float* __restrict__ x, float* __restrict__ xp) {
    int idx = blockIdx.x * 256 + threadIdx.x;
    if (idx < M_NODE * 32) {
        int m = idx >> 5, c = idx & 31;
        xp[idx] = (c < 6) ? x[m * 6 + c] : 0.f;
    }
}

// ---------------- BN finalize ------------------------------------------------
__global__ void bn_finalize(const float* __restrict__ psum, const float* __restrict__ psq,
                            int nblocks, float Minv,
                            const float* __restrict__ g, const float* __restrict__ be,
                            float* __restrict__ s, float* __restrict__ t)
{
    int c = threadIdx.x;
    float S = 0.f, Q = 0.f;
    for (int i = 0; i < nblocks; i++) {
        S += psum[(size_t)i * 128 + c];
        Q += psq [(size_t)i * 128 + c];
    }
    float mean = S * Minv;
    float var  = Q * Minv - mean * mean;
    float inv  = rsqrtf(var + BN_EPS);
    float sv   = g[c] * inv;
    s[c] = sv;
    t[c] = be[c] - mean * sv;
}

// ---------------- edge2node --------------------------------------------------
__global__ void edge2node(const float* __restrict__ h,
                          const float* __restrict__ s, const float* __restrict__ t,
                          float* __restrict__ outn)
{
    int c  = threadIdx.x;
    int bn = blockIdx.x;
    const float* p = h + (size_t)bn * 23 * 128 + c;
    float acc = 0.f;
#pragma unroll
    for (int j = 0; j < 23; j++) acc += p[(size_t)j * 128];
    outn[(size_t)bn * 128 + c] = (s[c] * acc + 23.f * t[c]) * (1.f / 24.f);
}

// ---------------- final projection -------------------------------------------
__global__ void final_proj(const float* __restrict__ node4,
                           const float* __restrict__ fo_w, const float* __restrict__ fo_b,
                           float* __restrict__ out)
{
    int b = blockIdx.x;
    int c = threadIdx.x;
    float a0 = 0.f, a1 = 0.f;
#pragma unroll
    for (int n = 0; n < NKPS; n++) {
        float v = node4[((size_t)b * NKPS + n) * 128 + c];
        a0 = fmaf(v, fo_w[n * 128 + c],        a0);
        a1 = fmaf(v, fo_w[3072 + n * 128 + c], a1);
    }
    __shared__ float r0[128], r1[128];
    r0[c] = a0; r1[c] = a1;
    __syncthreads();
    for (int off = 64; off; off >>= 1) {
        if (c < off) { r0[c] += r0[c + off]; r1[c] += r1[c + off]; }
        __syncthreads();
    }
    if (c == 0) {
        out[b * 2 + 0] = r0[0] + fo_b[0];
        out[b * 2 + 1] = r1[0] + fo_b[1];
    }
}

// ---------------- launch ------------------------------------------------------
extern "C" void kernel_launch(void* const* d_in, const int* in_sizes, int n_in,
                              void* d_out, int out_size)
{
    const float* inputs = (const float*)d_in[0];
    const float* fo_w = (const float*)d_in[3];
    const float* fo_b = (const float*)d_in[4];
    const float* m1w1 = (const float*)d_in[5];
    const float* m1b1 = (const float*)d_in[6];
    const float* m1w2 = (const float*)d_in[7];
    const float* m1b2 = (const float*)d_in[8];
    const float* m1g  = (const float*)d_in[9];
    const float* m1be = (const float*)d_in[10];
    const float* m2w1 = (const float*)d_in[11];
    const float* m2b1 = (const float*)d_in[12];
    const float* m2w2 = (const float*)d_in[13];
    const float* m2b2 = (const float*)d_in[14];
    const float* m2g  = (const float*)d_in[15];
    const float* m2be = (const float*)d_in[16];
    const float* m3w1 = (const float*)d_in[17];
    const float* m3b1 = (const float*)d_in[18];
    const float* m3w2 = (const float*)d_in[19];
    const float* m3b2 = (const float*)d_in[20];
    const float* m3g  = (const float*)d_in[21];
    const float* m3be = (const float*)d_in[22];
    const float* m4w1 = (const float*)d_in[23];
    const float* m4b1 = (const float*)d_in[24];
    const float* m4w2 = (const float*)d_in[25];
    const float* m4b2 = (const float*)d_in[26];
    const float* m4g  = (const float*)d_in[27];
    const float* m4be = (const float*)d_in[28];
    float* out = (float*)d_out;

    float *bufA, *bufB, *n1, *n2, *n3, *xpad, *w1e, *beff, *psum, *psq, *sArr, *tArr;
    cudaGetSymbolAddress((void**)&bufA, g_bufA);
    cudaGetSymbolAddress((void**)&bufB, g_bufB);
    cudaGetSymbolAddress((void**)&n1,   g_n1);
    cudaGetSymbolAddress((void**)&n2,   g_n2);
    cudaGetSymbolAddress((void**)&n3,   g_n3);
    cudaGetSymbolAddress((void**)&xpad, g_xpad);
    cudaGetSymbolAddress((void**)&w1e,  g_w1e);
    cudaGetSymbolAddress((void**)&beff, g_beff);
    cudaGetSymbolAddress((void**)&psum, g_psum);
    cudaGetSymbolAddress((void**)&psq,  g_psq);
    cudaGetSymbolAddress((void**)&sArr, g_s);
    cudaGetSymbolAddress((void**)&tArr, g_t);

    cudaFuncSetAttribute(mlp2<0,32>,  cudaFuncAttributeMaxDynamicSharedMemorySize, SMEM_TOTAL);
    cudaFuncSetAttribute(mlp2<0,128>, cudaFuncAttributeMaxDynamicSharedMemorySize, SMEM_TOTAL);
    cudaFuncSetAttribute(mlp2<2,256>, cudaFuncAttributeMaxDynamicSharedMemorySize, SMEM_TOTAL);
    cudaFuncSetAttribute(mlp2<3,384>, cudaFuncAttributeMaxDynamicSharedMemorySize, SMEM_TOTAL);

    const int GN = M_NODE / 128;   // 192
    const int GE = M_EDGE / 128;   // 4416
    const float MinvN = 1.0f / (float)M_NODE;
    const float MinvE = 1.0f / (float)M_EDGE;

    // stage 1 (nodes): pad inputs, fold (identity) weights, fused MLP, BN
    pad_inputs<<<(M_NODE * 32 + 255) / 256, 256>>>(inputs, xpad);
    prep_w<<<128, 256>>>(m1w1, m1b1, 6, 32, nullptr, nullptr, nullptr, nullptr, w1e, beff);
    mlp2<0,32><<<GN, 256, SMEM_TOTAL>>>(xpad, nullptr, w1e, beff, m1w2, m1b2,
                                        n1, psum, psq);
    bn_finalize<<<1, 128>>>(psum, psq, GN, MinvN, m1g, m1be, sArr + 0, tArr + 0);

    // stage 2 (edges): fold BN1 into W, gathered fused MLP, BN
    prep_w<<<128, 256>>>(m2w1, m2b1, 256, 256, sArr + 0, tArr + 0, nullptr, nullptr, w1e, beff);
    mlp2<2,256><<<GE, 256, SMEM_TOTAL>>>(n1, nullptr, w1e, beff, m2w2, m2b2,
                                         bufA, psum, psq);
    bn_finalize<<<1, 128>>>(psum, psq, GE, MinvE, m2g, m2be, sArr + 128, tArr + 128);

    edge2node<<<M_NODE, 128>>>(bufA, sArr + 128, tArr + 128, n2);

    // stage 3 (nodes)
    prep_w<<<128, 256>>>(m3w1, m3b1, 128, 128, nullptr, nullptr, nullptr, nullptr, w1e, beff);
    mlp2<0,128><<<GN, 256, SMEM_TOTAL>>>(n2, nullptr, w1e, beff, m3w2, m3b2,
                                         n3, psum, psq);
    bn_finalize<<<1, 128>>>(psum, psq, GN, MinvN, m3g, m3be, sArr + 256, tArr + 256);

    // stage 4 (edges, with skip): fold BN3 (k<256) + BN2 (skip) into W
    prep_w<<<128, 256>>>(m4w1, m4b1, 384, 384, sArr + 256, tArr + 256, sArr + 128, tArr + 128, w1e, beff);
    mlp2<3,384><<<GE, 256, SMEM_TOTAL>>>(n3, bufA, w1e, beff, m4w2, m4b2,
                                         bufB, psum, psq);
    bn_finalize<<<1, 128>>>(psum, psq, GE, MinvE, m4g, m4be, sArr + 384, tArr + 384);

    edge2node<<<M_NODE, 128>>>(bufB, sArr + 384, tArr + 384, n2);
    final_proj<<<BATCH, 128>>>(n2, fo_w, fo_b, out);
}

// round 4
// speedup vs baseline: 2.7590x; 1.6680x over previous
#include <cuda_runtime.h>
#include <math.h>
#include <stdint.h>

#define BATCH   1024
#define NKPS    24
#define NEDGE   552
#define M_NODE  (BATCH*NKPS)    // 24576
#define M_EDGE  (BATCH*NEDGE)   // 565248
#define BN_EPS  1e-5f

// ---------------- scratch (device globals) ---------------------------------
__device__ float g_bufA[(size_t)M_EDGE*128];   // h2 (x_skip), tf32-rounded
__device__ float g_bufB[(size_t)M_EDGE*128];   // h4, full fp32
__device__ float g_n1 [(size_t)M_NODE*128];    // h1, tf32-rounded
__device__ float g_n2 [(size_t)M_NODE*128];    // node2 (rounded) / node4 (fp32)
__device__ float g_n3 [(size_t)M_NODE*128];    // h3, tf32-rounded
__device__ float g_w1e[384*128];               // folded+rounded layer-1 weights
__device__ float g_w2e[128*128];               // rounded layer-2 weights
__device__ float g_beff[128];                  // folded layer-1 bias (fp32)
__device__ float g_psum[(M_EDGE/128)*128];
__device__ float g_psq [(M_EDGE/128)*128];
__device__ float g_s[4*128];
__device__ float g_t[4*128];

// ---------------- small helpers ---------------------------------------------
__device__ __forceinline__ uint32_t smem_u32(const void* p) {
    uint32_t a;
    asm("{ .reg .u64 t; cvta.to.shared.u64 t, %1; cvt.u32.u64 %0, t; }" : "=r"(a) : "l"(p));
    return a;
}
__device__ __forceinline__ void cp16(uint32_t dst, const void* src) {
    asm volatile("cp.async.cg.shared.global [%0], [%1], 16;" :: "r"(dst), "l"(src));
}
__device__ __forceinline__ uint32_t f2tf(float x) {
    uint32_t u;
    asm("cvt.rna.tf32.f32 %0, %1;" : "=r"(u) : "f"(x));
    return u;
}
__device__ __forceinline__ void mma8(float d[4],
                                     uint32_t a0, uint32_t a1, uint32_t a2, uint32_t a3,
                                     uint32_t b0, uint32_t b1) {
    asm volatile("mma.sync.aligned.m16n8k8.row.col.f32.tf32.tf32.f32 "
        "{%0,%1,%2,%3}, {%4,%5,%6,%7}, {%8,%9}, {%0,%1,%2,%3};"
        : "+f"(d[0]), "+f"(d[1]), "+f"(d[2]), "+f"(d[3])
        : "r"(a0), "r"(a1), "r"(a2), "r"(a3), "r"(b0), "r"(b1));
}

// ---------------- SMEM layout (bytes) ----------------------------------------
// chunk buffers: [128 rows][20-float stride] = 10240B each, 2 A + 2 W
// A2: [128][132-float stride] = 67584B
#define OFF_RECV   0
#define OFF_SEND   512
#define OFF_BE     1024
#define OFF_B2V    1536
#define OFF_CHA    2048                 /* 2 x 10240 */
#define OFF_CHW    22528                /* 2 x 10240 */
#define OFF_A2     43008                /* 67584 */
#define SMEM_TOTAL 110592

// ---------------- fused 2-layer MLP, mma.sync tf32 ---------------------------
// MODE 1: stage-1 special: A = raw inputs [M][6], W1/W2 raw (rounded inline)
// MODE 0: A plain [M][K1PAD], pre-rounded
// MODE 2: edge gather K1=256 (recv|send rows of A[M_NODE][128]), pre-rounded
// MODE 3: edge gather K1=384 (recv|send of A + skip rows of Askip), pre-rounded
template<int MODE, int K1PAD, bool ROUND_OUT, bool CVT_B2>
__global__ __launch_bounds__(256, 2)
void mlp2(const float* __restrict__ A, const float* __restrict__ Askip,
          const float* __restrict__ W1e, const float* __restrict__ beff,
          const float* __restrict__ W2e, const float* __restrict__ b2,
          float* __restrict__ out,
          float* __restrict__ psum, float* __restrict__ psq)
{
    extern __shared__ char smem[];
    float* smf = (float*)smem;
    const uint32_t sb = smem_u32(smem);
    const int tid = threadIdx.x;
    const int wid = tid >> 5, lid = tid & 31;
    const int g = lid >> 2, tg = lid & 3;
    const int wm = wid & 3, wn = wid >> 2;       // warp tile: rows wm*32, cols wn*64
    const int row0 = blockIdx.x * 128;
    int* rs = (int*)(smem + OFF_RECV);
    int* ss = (int*)(smem + OFF_SEND);

    if ((MODE == 2 || MODE == 3) && tid < 128) {
        int row = row0 + tid;
        int b = row / NEDGE;
        int e = row - b * NEDGE;
        int r = e / 23;
        int j = e - r * 23;
        int s = j + (j >= r);
        rs[tid] = b * NKPS + r;
        ss[tid] = b * NKPS + s;
    }
    if (tid < 128) {
        smf[OFF_BE/4  + tid] = beff[tid];
        smf[OFF_B2V/4 + tid] = b2[tid];
    }
    __syncthreads();

    float acc[2][8][4];
#pragma unroll
    for (int f = 0; f < 2; f++)
#pragma unroll
        for (int nt = 0; nt < 8; nt++)
#pragma unroll
            for (int q = 0; q < 4; q++) acc[f][nt][q] = 0.f;

    // ================= LAYER 1 =================
    if (MODE == 1) {
        // inline fill: pad K 6->16, round to tf32
#pragma unroll
        for (int i = 0; i < 8; i++) {
            int idx = i * 256 + tid;              // 2048 elems
            int row = idx >> 4, col = idx & 15;
            float av = (col < 6) ? A[(size_t)(row0 + row) * 6 + col] : 0.f;
            float wv = (col < 6) ? W1e[row * 6 + col] : 0.f;   // W1 raw [128][6]
            smf[OFF_CHA/4 + row * 20 + col] = __uint_as_float(f2tf(av));
            smf[OFF_CHW/4 + row * 20 + col] = __uint_as_float(f2tf(wv));
        }
        __syncthreads();
        const uint32_t* As = (const uint32_t*)(smem + OFF_CHA);
        const uint32_t* Ws = (const uint32_t*)(smem + OFF_CHW);
#pragma unroll
        for (int ks = 0; ks < 2; ks++) {
            uint32_t a[2][4];
#pragma unroll
            for (int f = 0; f < 2; f++) {
                const uint32_t* p = As + (wm * 32 + f * 16 + g) * 20 + ks * 8 + tg;
                a[f][0] = p[0]; a[f][1] = p[8 * 20]; a[f][2] = p[4]; a[f][3] = p[8 * 20 + 4];
            }
#pragma unroll
            for (int nt = 0; nt < 8; nt++) {
                const uint32_t* q = Ws + (wn * 64 + nt * 8 + g) * 20 + ks * 8 + tg;
                uint32_t b0 = q[0], b1 = q[4];
                mma8(acc[0][nt], a[0][0], a[0][1], a[0][2], a[0][3], b0, b1);
                mma8(acc[1][nt], a[1][0], a[1][1], a[1][2], a[1][3], b0, b1);
            }
        }
        __syncthreads();
    } else {
        constexpr int NCH = K1PAD / 16;
        auto issue_chunk = [&](int c, int buf) {
            const int kb = c * 16;
#pragma unroll
            for (int i = 0; i < 2; i++) {
                int idx4 = i * 256 + tid;          // 512 float4
                int row = idx4 >> 2, c4 = idx4 & 3;
                int kk = kb + c4 * 4;
                const float* src;
                if (MODE == 0) {
                    src = A + (size_t)(row0 + row) * K1PAD + kk;
                } else {
                    if (kk < 128)      src = A + (size_t)rs[row] * 128 + kk;
                    else if (kk < 256) src = A + (size_t)ss[row] * 128 + (kk - 128);
                    else               src = Askip + (size_t)(row0 + row) * 128 + (kk - 256);
                }
                cp16(sb + OFF_CHA + buf * 10240 + row * 80 + c4 * 16, src);
                cp16(sb + OFF_CHW + buf * 10240 + row * 80 + c4 * 16,
                     W1e + (size_t)row * K1PAD + kk);
            }
            asm volatile("cp.async.commit_group;");
        };
        issue_chunk(0, 0);
        if (NCH > 1) issue_chunk(1, 1);
        for (int c = 0; c < NCH; c++) {
            const int buf = c & 1;
            if (c + 1 < NCH) asm volatile("cp.async.wait_group 1;");
            else             asm volatile("cp.async.wait_group 0;");
            __syncthreads();
            const uint32_t* As = (const uint32_t*)(smem + OFF_CHA + buf * 10240);
            const uint32_t* Ws = (const uint32_t*)(smem + OFF_CHW + buf * 10240);
#pragma unroll
            for (int ks = 0; ks < 2; ks++) {
                uint32_t a[2][4];
#pragma unroll
                for (int f = 0; f < 2; f++) {
                    const uint32_t* p = As + (wm * 32 + f * 16 + g) * 20 + ks * 8 + tg;
                    a[f][0] = p[0]; a[f][1] = p[8 * 20]; a[f][2] = p[4]; a[f][3] = p[8 * 20 + 4];
                }
#pragma unroll
                for (int nt = 0; nt < 8; nt++) {
                    const uint32_t* q = Ws + (wn * 64 + nt * 8 + g) * 20 + ks * 8 + tg;
                    uint32_t b0 = q[0], b1 = q[4];
                    mma8(acc[0][nt], a[0][0], a[0][1], a[0][2], a[0][3], b0, b1);
                    mma8(acc[1][nt], a[1][0], a[1][1], a[1][2], a[1][3], b0, b1);
                }
            }
            __syncthreads();
            if (c + 2 < NCH) issue_chunk(c + 2, buf);
        }
    }

    // ---- prefetch W2 chunks 0,1 (overlap with epilogue 1) ----
    auto issue_w2 = [&](int c, int buf) {
#pragma unroll
        for (int i = 0; i < 2; i++) {
            int idx4 = i * 256 + tid;
            int row = idx4 >> 2, c4 = idx4 & 3;
            int kk = c * 16 + c4 * 4;
            cp16(sb + OFF_CHW + buf * 10240 + row * 80 + c4 * 16,
                 W2e + (size_t)row * 128 + kk);
        }
        asm volatile("cp.async.commit_group;");
    };
    issue_w2(0, 0);
    issue_w2(1, 1);

    // ---- epilogue 1: bias + ELU -> A2 (tf32-rounded), reset acc ----
    {
        float* A2 = smf + OFF_A2 / 4;
#pragma unroll
        for (int f = 0; f < 2; f++) {
            int r = wm * 32 + f * 16 + g;
#pragma unroll
            for (int nt = 0; nt < 8; nt++) {
                int n0 = wn * 64 + nt * 8 + tg * 2;
                float be0 = smf[OFF_BE/4 + n0], be1 = smf[OFF_BE/4 + n0 + 1];
                float v0 = acc[f][nt][0] + be0;
                float v1 = acc[f][nt][1] + be1;
                float v2 = acc[f][nt][2] + be0;
                float v3 = acc[f][nt][3] + be1;
                v0 = (v0 > 0.f) ? v0 : expm1f(v0);
                v1 = (v1 > 0.f) ? v1 : expm1f(v1);
                v2 = (v2 > 0.f) ? v2 : expm1f(v2);
                v3 = (v3 > 0.f) ? v3 : expm1f(v3);
                *(float2*)(A2 + r * 132 + n0) =
                    make_float2(__uint_as_float(f2tf(v0)), __uint_as_float(f2tf(v1)));
                *(float2*)(A2 + (r + 8) * 132 + n0) =
                    make_float2(__uint_as_float(f2tf(v2)), __uint_as_float(f2tf(v3)));
#pragma unroll
                for (int q = 0; q < 4; q++) acc[f][nt][q] = 0.f;
            }
        }
    }
    __syncthreads();

    // ================= LAYER 2 (W2 streamed, A2 resident) =================
    for (int c = 0; c < 8; c++) {
        const int buf = c & 1;
        if (c < 7) asm volatile("cp.async.wait_group 1;");
        else       asm volatile("cp.async.wait_group 0;");
        __syncthreads();
        const uint32_t* As = (const uint32_t*)(smem + OFF_A2);
        const char* Wb = smem + OFF_CHW + buf * 10240;
#pragma unroll
        for (int ks = 0; ks < 2; ks++) {
            uint32_t a[2][4];
#pragma unroll
            for (int f = 0; f < 2; f++) {
                const uint32_t* p = As + (wm * 32 + f * 16 + g) * 132 + c * 16 + ks * 8 + tg;
                a[f][0] = p[0]; a[f][1] = p[8 * 132]; a[f][2] = p[4]; a[f][3] = p[8 * 132 + 4];
            }
#pragma unroll
            for (int nt = 0; nt < 8; nt++) {
                uint32_t b0, b1;
                if (CVT_B2) {
                    const float* q = (const float*)Wb + (wn * 64 + nt * 8 + g) * 20 + ks * 8 + tg;
                    b0 = f2tf(q[0]); b1 = f2tf(q[4]);
                } else {
                    const uint32_t* q = (const uint32_t*)Wb + (wn * 64 + nt * 8 + g) * 20 + ks * 8 + tg;
                    b0 = q[0]; b1 = q[4];
                }
                mma8(acc[0][nt], a[0][0], a[0][1], a[0][2], a[0][3], b0, b1);
                mma8(acc[1][nt], a[1][0], a[1][1], a[1][2], a[1][3], b0, b1);
            }
        }
        __syncthreads();
        if (c + 2 < 8) issue_w2(c + 2, buf);
    }

    // ---- epilogue 2: bias + ELU -> A2 staging, then store + stats ----
    {
        float* A2 = smf + OFF_A2 / 4;
#pragma unroll
        for (int f = 0; f < 2; f++) {
            int r = wm * 32 + f * 16 + g;
#pragma unroll
            for (int nt = 0; nt < 8; nt++) {
                int n0 = wn * 64 + nt * 8 + tg * 2;
                float be0 = smf[OFF_B2V/4 + n0], be1 = smf[OFF_B2V/4 + n0 + 1];
                float v0 = acc[f][nt][0] + be0;
                float v1 = acc[f][nt][1] + be1;
                float v2 = acc[f][nt][2] + be0;
                float v3 = acc[f][nt][3] + be1;
                v0 = (v0 > 0.f) ? v0 : expm1f(v0);
                v1 = (v1 > 0.f) ? v1 : expm1f(v1);
                v2 = (v2 > 0.f) ? v2 : expm1f(v2);
                v3 = (v3 > 0.f) ? v3 : expm1f(v3);
                if (ROUND_OUT) {
                    v0 = __uint_as_float(f2tf(v0));
                    v1 = __uint_as_float(f2tf(v1));
                    v2 = __uint_as_float(f2tf(v2));
                    v3 = __uint_as_float(f2tf(v3));
                }
                *(float2*)(A2 + r * 132 + n0)       = make_float2(v0, v1);
                *(float2*)(A2 + (r + 8) * 132 + n0) = make_float2(v2, v3);
            }
        }
    }
    __syncthreads();
    {
        const float* A2 = smf + OFF_A2 / 4;
#pragma unroll
        for (int i = 0; i < 16; i++) {
            int idx4 = i * 256 + tid;
            int row = idx4 >> 5, c4 = idx4 & 31;
            float4 v = *(const float4*)(A2 + row * 132 + c4 * 4);
            *(float4*)(out + (size_t)(row0 + row) * 128 + c4 * 4) = v;
        }
        if (tid < 128) {
            float S = 0.f, Q = 0.f;
#pragma unroll 8
            for (int r = 0; r < 128; r++) {
                float x = A2[r * 132 + tid];
                S += x;
                Q += x * x;
            }
            psum[(size_t)blockIdx.x * 128 + tid] = S;
            psq [(size_t)blockIdx.x * 128 + tid] = Q;
        }
    }
}

// ---------------- prep: fold BN affine into layer-1 weights, round both ------
// blocks 0..127: W1e[n][k] = round(W1[n][k]*s(k)); beff[n] = b1[n] + sum W1[n][k]*t(k)
// blocks 128..191: W2e = round(W2)
__global__ void prep(const float* __restrict__ W1, const float* __restrict__ b1,
                     int k1real, int K1PAD,
                     const float* __restrict__ sA, const float* __restrict__ tA,
                     const float* __restrict__ sB, const float* __restrict__ tB,
                     const float* __restrict__ W2,
                     float* __restrict__ W1e, float* __restrict__ beff,
                     float* __restrict__ W2e)
{
    const int tid = threadIdx.x;
    if (blockIdx.x < 128) {
        const int n = blockIdx.x;
        float partial = 0.f;
        for (int k = tid; k < K1PAD; k += 256) {
            float w = (k < k1real) ? W1[(size_t)n * k1real + k] : 0.f;
            float s = 1.f, t = 0.f;
            if (k < k1real) {
                if (k < 256) { if (sA) { s = sA[k & 127]; t = tA[k & 127]; } }
                else         { s = sB[k - 256]; t = tB[k - 256]; }
            }
            float u;
            asm("cvt.rna.tf32.f32 %0, %1;" : "=f"(u) : "f"(w * s));
            W1e[(size_t)n * K1PAD + k] = u;
            partial += w * t;
        }
        __shared__ float red[256];
        red[tid] = partial;
        __syncthreads();
        for (int off = 128; off; off >>= 1) {
            if (tid < off) red[tid] += red[tid + off];
            __syncthreads();
        }
        if (tid == 0) beff[n] = b1[n] + red[0];
    } else {
        int idx = (blockIdx.x - 128) * 256 + tid;
        float u;
        asm("cvt.rna.tf32.f32 %0, %1;" : "=f"(u) : "f"(W2[idx]));
        W2e[idx] = u;
    }
}

// ---------------- BN finalize (grid=1, 1024 threads, coalesced) --------------
__global__ void bn_finalize(const float* __restrict__ psum, const float* __restrict__ psq,
                            int nblocks, float Minv,
                            const float* __restrict__ g, const float* __restrict__ be,
                            float* __restrict__ s, float* __restrict__ t)
{
    const int tid = threadIdx.x;
    const int c = tid & 127, part = tid >> 7;   // 8 partitions
    float S = 0.f, Q = 0.f;
    for (int i = part; i < nblocks; i += 8) {
        S += psum[(size_t)i * 128 + c];
        Q += psq [(size_t)i * 128 + c];
    }
    __shared__ float sS[8][128], sQ[8][128];
    sS[part][c] = S;
    sQ[part][c] = Q;
    __syncthreads();
    if (tid < 128) {
        float St = 0.f, Qt = 0.f;
#pragma unroll
        for (int p = 0; p < 8; p++) { St += sS[p][tid]; Qt += sQ[p][tid]; }
        float mean = St * Minv;
        float var  = Qt * Minv - mean * mean;
        float inv  = rsqrtf(var + BN_EPS);
        float sv   = g[tid] * inv;
        s[tid] = sv;
        t[tid] = be[tid] - mean * sv;
    }
}

// ---------------- edge2node (optionally tf32-round output) -------------------
template<bool R>
__global__ void edge2node(const float* __restrict__ h,
                          const float* __restrict__ s, const float* __restrict__ t,
                          float* __restrict__ outn)
{
    int c  = threadIdx.x;
    int bn = blockIdx.x;
    const float* p = h + (size_t)bn * 23 * 128 + c;
    float acc = 0.f;
#pragma unroll
    for (int j = 0; j < 23; j++) acc += p[(size_t)j * 128];
    float val = (s[c] * acc + 23.f * t[c]) * (1.f / 24.f);
    if (R) val = __uint_as_float(f2tf(val));
    outn[(size_t)bn * 128 + c] = val;
}

// ---------------- final projection -------------------------------------------
__global__ void final_proj(const float* __restrict__ node4,
                           const float* __restrict__ fo_w, const float* __restrict__ fo_b,
                           float* __restrict__ out)
{
    int b = blockIdx.x;
    int c = threadIdx.x;
    float a0 = 0.f, a1 = 0.f;
#pragma unroll
    for (int n = 0; n < NKPS; n++) {
        float v = node4[((size_t)b * NKPS + n) * 128 + c];
        a0 = fmaf(v, fo_w[n * 128 + c],        a0);
        a1 = fmaf(v, fo_w[3072 + n * 128 + c], a1);
    }
    __shared__ float r0[128], r1[128];
    r0[c] = a0; r1[c] = a1;
    __syncthreads();
    for (int off = 64; off; off >>= 1) {
        if (c < off) { r0[c] += r0[c + off]; r1[c] += r1[c + off]; }
        __syncthreads();
    }
    if (c == 0) {
        out[b * 2 + 0] = r0[0] + fo_b[0];
        out[b * 2 + 1] = r1[0] + fo_b[1];
    }
}

// ---------------- launch ------------------------------------------------------
extern "C" void kernel_launch(void* const* d_in, const int* in_sizes, int n_in,
                              void* d_out, int out_size)
{
    const float* inputs = (const float*)d_in[0];
    const float* fo_w = (const float*)d_in[3];
    const float* fo_b = (const float*)d_in[4];
    const float* m1w1 = (const float*)d_in[5];
    const float* m1b1 = (const float*)d_in[6];
    const float* m1w2 = (const float*)d_in[7];
    const float* m1b2 = (const float*)d_in[8];
    const float* m1g  = (const float*)d_in[9];
    const float* m1be = (const float*)d_in[10];
    const float* m2w1 = (const float*)d_in[11];
    const float* m2b1 = (const float*)d_in[12];
    const float* m2w2 = (const float*)d_in[13];
    const float* m2b2 = (const float*)d_in[14];
    const float* m2g  = (const float*)d_in[15];
    const float* m2be = (const float*)d_in[16];
    const float* m3w1 = (const float*)d_in[17];
    const float* m3b1 = (const float*)d_in[18];
    const float* m3w2 = (const float*)d_in[19];
    const float* m3b2 = (const float*)d_in[20];
    const float* m3g  = (const float*)d_in[21];
    const float* m3be = (const float*)d_in[22];
    const float* m4w1 = (const float*)d_in[23];
    const float* m4b1 = (const float*)d_in[24];
    const float* m4w2 = (const float*)d_in[25];
    const float* m4b2 = (const float*)d_in[26];
    const float* m4g  = (const float*)d_in[27];
    const float* m4be = (const float*)d_in[28];
    float* out = (float*)d_out;

    float *bufA, *bufB, *n1, *n2, *n3, *w1e, *w2e, *beff, *psum, *psq, *sArr, *tArr;
    cudaGetSymbolAddress((void**)&bufA, g_bufA);
    cudaGetSymbolAddress((void**)&bufB, g_bufB);
    cudaGetSymbolAddress((void**)&n1,   g_n1);
    cudaGetSymbolAddress((void**)&n2,   g_n2);
    cudaGetSymbolAddress((void**)&n3,   g_n3);
    cudaGetSymbolAddress((void**)&w1e,  g_w1e);
    cudaGetSymbolAddress((void**)&w2e,  g_w2e);
    cudaGetSymbolAddress((void**)&beff, g_beff);
    cudaGetSymbolAddress((void**)&psum, g_psum);
    cudaGetSymbolAddress((void**)&psq,  g_psq);
    cudaGetSymbolAddress((void**)&sArr, g_s);
    cudaGetSymbolAddress((void**)&tArr, g_t);

    cudaFuncSetAttribute(mlp2<1,16,true,true>,   cudaFuncAttributeMaxDynamicSharedMemorySize, SMEM_TOTAL);
    cudaFuncSetAttribute(mlp2<2,256,true,false>, cudaFuncAttributeMaxDynamicSharedMemorySize, SMEM_TOTAL);
    cudaFuncSetAttribute(mlp2<0,128,true,false>, cudaFuncAttributeMaxDynamicSharedMemorySize, SMEM_TOTAL);
    cudaFuncSetAttribute(mlp2<3,384,false,false>,cudaFuncAttributeMaxDynamicSharedMemorySize, SMEM_TOTAL);

    const int GN = M_NODE / 128;   // 192
    const int GE = M_EDGE / 128;   // 4416
    const float MinvN = 1.0f / (float)M_NODE;
    const float MinvE = 1.0f / (float)M_EDGE;

    // stage 1 (nodes): inline-prep MLP (raw W, raw inputs), BN -> s/t[0]
    mlp2<1,16,true,true><<<GN, 256, SMEM_TOTAL>>>(inputs, nullptr, m1w1, m1b1,
                                                  m1w2, m1b2, n1, psum, psq);
    bn_finalize<<<1, 1024>>>(psum, psq, GN, MinvN, m1g, m1be, sArr + 0, tArr + 0);

    // stage 2 (edges): fold BN1, gathered fused MLP, BN -> s/t[1]
    prep<<<192, 256>>>(m2w1, m2b1, 256, 256, sArr + 0, tArr + 0, nullptr, nullptr,
                       m2w2, w1e, beff, w2e);
    mlp2<2,256,true,false><<<GE, 256, SMEM_TOTAL>>>(n1, nullptr, w1e, beff,
                                                    w2e, m2b2, bufA, psum, psq);
    bn_finalize<<<1, 1024>>>(psum, psq, GE, MinvE, m2g, m2be, sArr + 128, tArr + 128);

    edge2node<true><<<M_NODE, 128>>>(bufA, sArr + 128, tArr + 128, n2);

    // stage 3 (nodes)
    prep<<<192, 256>>>(m3w1, m3b1, 128, 128, nullptr, nullptr, nullptr, nullptr,
                       m3w2, w1e, beff, w2e);
    mlp2<0,128,true,false><<<GN, 256, SMEM_TOTAL>>>(n2, nullptr, w1e, beff,
                                                    w2e, m3b2, n3, psum, psq);
    bn_finalize<<<1, 1024>>>(psum, psq, GN, MinvN, m3g, m3be, sArr + 256, tArr + 256);

    // stage 4 (edges + skip): fold BN3 (k<256) + BN2 (skip)
    prep<<<192, 256>>>(m4w1, m4b1, 384, 384, sArr + 256, tArr + 256, sArr + 128, tArr + 128,
                       m4w2, w1e, beff, w2e);
    mlp2<3,384,false,false><<<GE, 256, SMEM_TOTAL>>>(n3, bufA, w1e, beff,
                                                     w2e, m4b2, bufB, psum, psq);
    bn_finalize<<<1, 1024>>>(psum, psq, GE, MinvE, m4g, m4be, sArr + 384, tArr + 384);

    edge2node<false><<<M_NODE, 128>>>(bufB, sArr + 384, tArr + 384, n2);
    final_proj<<<BATCH, 128>>>(n2, fo_w, fo_b, out);
}